// round 3
// baseline (speedup 1.0000x reference)
#include <cuda_runtime.h>

// ---------------------------------------------------------------------------
// SSIM fusion loss:  1 - (SSIM(f,s1) + SSIM(f,s2)) / 2
// Separable 11-tap Gaussian blur, packed f32x2 FMA (FFMA2) for both passes.
// Deterministic integer fixed-point global reduction (no finalize scan).
// ---------------------------------------------------------------------------

#define IMH 512
#define IMW 512
#define NPLANES 48              // B*C = 16*3
#define TW 32
#define TH 32
#define EXT 42                  // TH + 10
#define RSTR 43                 // raw tile row stride (floats, odd -> conflict free)
#define HSTRU 37                // intermediate row stride in u64 (conflict-free stores)
#define NTHREADS 256
#define GX 16
#define GY 16
#define NTOT 12582912.0         // 16*3*512*512
#define FPSCALE 4294967296.0    // 2^32 fixed point

// raw region: 3*EXT*RSTR = 5418 floats, pad to 5420 (8B alignment for u64 region)
#define RAW_FLOATS 5420
#define HINT_U64   (4 * EXT * HSTRU)
#define SMEM_BYTES (RAW_FLOATS * 4 + HINT_U64 * 8)

typedef unsigned long long u64;

__device__ u64 g_acc = 0ULL;    // Q32.32 fixed-point sum of (ssim1+ssim2)

// ---- packed f32x2 helpers -------------------------------------------------
__device__ __forceinline__ u64 pack2(float lo, float hi) {
    u64 r;
    asm("mov.b64 %0, {%1, %2};" : "=l"(r)
        : "r"(__float_as_uint(lo)), "r"(__float_as_uint(hi)));
    return r;
}
__device__ __forceinline__ void unpack2(u64 v, float& lo, float& hi) {
    unsigned a, b;
    asm("mov.b64 {%0, %1}, %2;" : "=r"(a), "=r"(b) : "l"(v));
    lo = __uint_as_float(a); hi = __uint_as_float(b);
}
__device__ __forceinline__ u64 fma2(u64 a, u64 b, u64 c) {
    u64 d;
    asm("fma.rn.f32x2 %0, %1, %2, %3;" : "=l"(d) : "l"(a), "l"(b), "l"(c));
    return d;
}
__device__ __forceinline__ u64 mul2(u64 a, u64 b) {
    u64 d;
    asm("mul.rn.f32x2 %0, %1, %2;" : "=l"(d) : "l"(a), "l"(b));
    return d;
}

__global__ __launch_bounds__(NTHREADS)
void ssim_tile_kernel(const float* __restrict__ F,
                      const float* __restrict__ S1,
                      const float* __restrict__ S2)
{
    extern __shared__ float smem[];
    float* raw  = smem;                                   // [3][EXT*RSTR]
    u64*   hint = (u64*)(smem + RAW_FLOATS);              // [4][EXT*HSTRU]

    const int tid = threadIdx.x;

    // --- Gaussian weights: 6 unique (symmetric), packed (w,w) --------------
    u64 wp[6];
    {
        float w[6]; float s = 0.f;
        #pragma unroll
        for (int j = 0; j < 6; ++j) {
            float d = (float)(j - 5);
            w[j] = expf(-d * d * (1.0f / 4.5f));
            s += (j < 5) ? 2.f * w[j] : w[j];
        }
        float inv = 1.0f / s;
        #pragma unroll
        for (int j = 0; j < 6; ++j) { w[j] *= inv; wp[j] = pack2(w[j], w[j]); }
    }

    const int bx = blockIdx.x, by = blockIdx.y, bz = blockIdx.z;
    const int plane = bz * (IMH * IMW);
    const int x0 = bx * TW - 5;
    const int y0 = by * TH - 5;

    // --- Load extended (42x42) tile of f, s1, s2 with zero padding ---------
    for (int idx = tid; idx < EXT * EXT; idx += NTHREADS) {
        int r = idx / EXT;
        int c = idx - r * EXT;
        int gy = y0 + r;
        int gx = x0 + c;
        bool ok = (gy >= 0) && (gy < IMH) && (gx >= 0) && (gx < IMW);
        int off = plane + gy * IMW + gx;
        raw[0 * EXT * RSTR + r * RSTR + c] = ok ? __ldg(F  + off) : 0.f;
        raw[1 * EXT * RSTR + r * RSTR + c] = ok ? __ldg(S1 + off) : 0.f;
        raw[2 * EXT * RSTR + r * RSTR + c] = ok ? __ldg(S2 + off) : 0.f;
    }
    __syncthreads();

    // --- Horizontal pass: packed pairs A=(f,s1) B=(s2,f2) C=(s1²,s2²) D=(fs1,fs2)
    for (int task = tid; task < EXT * 8; task += NTHREADS) {
        int r  = task >> 3;
        int g  = task & 7;
        int c0 = g * 4;

        u64 aA[4], aB[4], aC[4], aD[4];
        #pragma unroll
        for (int o = 0; o < 4; ++o) { aA[o]=0; aB[o]=0; aC[o]=0; aD[o]=0; }

        const float* r0p = &raw[0 * EXT * RSTR + r * RSTR + c0];
        const float* r1p = &raw[1 * EXT * RSTR + r * RSTR + c0];
        const float* r2p = &raw[2 * EXT * RSTR + r * RSTR + c0];

        #pragma unroll
        for (int cc = 0; cc < 15; ++cc) {
            float f = r0p[cc], a = r1p[cc], b = r2p[cc];
            u64 pA  = pack2(f, a);
            u64 pB  = pack2(b, f * f);
            u64 pab = pack2(a, b);
            u64 pC  = mul2(pab, pab);          // (a², b²)
            u64 pD  = mul2(pack2(f, f), pab);  // (fa, fb)
            #pragma unroll
            for (int o = 0; o < 4; ++o) {
                int j = cc - o;
                if (j >= 0 && j < 11) {
                    u64 w = wp[(j < 6) ? j : (10 - j)];
                    aA[o] = fma2(w, pA, aA[o]);
                    aB[o] = fma2(w, pB, aB[o]);
                    aC[o] = fma2(w, pC, aC[o]);
                    aD[o] = fma2(w, pD, aD[o]);
                }
            }
        }
        u64* h0 = &hint[0 * EXT * HSTRU + r * HSTRU + c0];
        u64* h1 = &hint[1 * EXT * HSTRU + r * HSTRU + c0];
        u64* h2 = &hint[2 * EXT * HSTRU + r * HSTRU + c0];
        u64* h3 = &hint[3 * EXT * HSTRU + r * HSTRU + c0];
        #pragma unroll
        for (int o = 0; o < 4; ++o) {
            h0[o] = aA[o]; h1[o] = aB[o]; h2[o] = aC[o]; h3[o] = aD[o];
        }
    }
    __syncthreads();

    // --- Vertical pass + SSIM: thread = 1 column x 4 output rows -----------
    const int col = tid & 31;
    const int r0v = (tid >> 5) * 4;

    u64 aA[4], aB[4], aC[4], aD[4];
    #pragma unroll
    for (int o = 0; o < 4; ++o) { aA[o]=0; aB[o]=0; aC[o]=0; aD[o]=0; }

    #pragma unroll
    for (int jj = 0; jj < 14; ++jj) {
        u64 vA = hint[0 * EXT * HSTRU + (r0v + jj) * HSTRU + col];
        u64 vB = hint[1 * EXT * HSTRU + (r0v + jj) * HSTRU + col];
        u64 vC = hint[2 * EXT * HSTRU + (r0v + jj) * HSTRU + col];
        u64 vD = hint[3 * EXT * HSTRU + (r0v + jj) * HSTRU + col];
        #pragma unroll
        for (int o = 0; o < 4; ++o) {
            int j = jj - o;
            if (j >= 0 && j < 11) {
                u64 w = wp[(j < 6) ? j : (10 - j)];
                aA[o] = fma2(w, vA, aA[o]);
                aB[o] = fma2(w, vB, aB[o]);
                aC[o] = fma2(w, vC, aC[o]);
                aD[o] = fma2(w, vD, aD[o]);
            }
        }
    }

    const float C1 = 1e-4f;
    const float C2 = 9e-4f;
    float lsum = 0.f;
    #pragma unroll
    for (int o = 0; o < 4; ++o) {
        float muF, mu1, mu2, eFF, e11, e22, eF1, eF2;
        unpack2(aA[o], muF, mu1);
        unpack2(aB[o], mu2, eFF);
        unpack2(aC[o], e11, e22);
        unpack2(aD[o], eF1, eF2);

        float mFF = muF * muF, m11 = mu1 * mu1, m22 = mu2 * mu2;
        float pF1 = muF * mu1, pF2 = muF * mu2;

        float sF  = eFF - mFF;
        float s11 = e11 - m11;
        float s22 = e22 - m22;
        float c1v = eF1 - pF1;
        float c2v = eF2 - pF2;

        float num1 = (2.f * pF1 + C1) * (2.f * c1v + C2);
        float den1 = (mFF + m11 + C1) * (sF + s11 + C2);
        float num2 = (2.f * pF2 + C1) * (2.f * c2v + C2);
        float den2 = (mFF + m22 + C1) * (sF + s22 + C2);

        lsum += __fdividef(num1 * den2 + num2 * den1, den1 * den2);
    }

    // --- Block reduction -> deterministic Q32 integer atomic ---------------
    #pragma unroll
    for (int off = 16; off > 0; off >>= 1)
        lsum += __shfl_xor_sync(0xffffffffu, lsum, off);

    __shared__ float warpsum[8];
    if ((tid & 31) == 0) warpsum[tid >> 5] = lsum;
    __syncthreads();
    if (tid == 0) {
        double s = 0.0;
        #pragma unroll
        for (int i = 0; i < 8; ++i) s += (double)warpsum[i];
        long long q = __double2ll_rn(s * FPSCALE);
        atomicAdd(&g_acc, (u64)q);
    }
}

__global__ void ssim_convert_kernel(float* __restrict__ out)
{
    long long v = (long long)g_acc;
    out[0] = (float)(1.0 - ((double)v * (1.0 / FPSCALE)) / (2.0 * NTOT));
    g_acc = 0ULL;   // reset for the next graph replay (deterministic sequence)
}

extern "C" void kernel_launch(void* const* d_in, const int* in_sizes, int n_in,
                              void* d_out, int out_size)
{
    const float* F  = (const float*)d_in[0];
    const float* S1 = (const float*)d_in[1];
    const float* S2 = (const float*)d_in[2];

    static bool attr_set = false;
    if (!attr_set) {
        cudaFuncSetAttribute(ssim_tile_kernel,
                             cudaFuncAttributeMaxDynamicSharedMemorySize,
                             SMEM_BYTES);
        attr_set = true;
    }

    dim3 grid(GX, GY, NPLANES);
    ssim_tile_kernel<<<grid, NTHREADS, SMEM_BYTES>>>(F, S1, S2);
    ssim_convert_kernel<<<1, 1>>>((float*)d_out);
}